// round 11
// baseline (speedup 1.0000x reference)
#include <cuda_runtime.h>
#include <cstdint>

// ============================================================================
// Geodesic patch conv via frequency domain (NDIRS=16 circular correlation):
//   Yhat[v,rc,b] = DFT_16(y[v,rc,:])  -> stored DUPLICATED (re,re,im,im)
//   out[v,j,f]   = relu( bias[f] + sum_b Re{ (sum_rc Yhat*G) e^{+i 2pi jb/16} } )
// P2 inner step: 2x LDS.128 + 4x FMA2, zero ALU packing (4-acc split:
//   p=SumYrGr, q=SumYiGi, r=SumYrGi, s=SumYiGr; Cr=p-q, Ci=r+s).
// ============================================================================

#define NVv     50000
#define NVERT   200000
#define VPB     32
#define THREADS 288            // 9 warps; 32*9=288 exact for P1b

// cos(k * 22.5 deg), k = 0..15.  sin(k*22.5) = C16[(k+12)&15]
__device__ constexpr float C16[16] = {
     1.0f,                  0.9238795325112867f,  0.7071067811865476f,  0.3826834323650898f,
     0.0f,                 -0.3826834323650898f, -0.7071067811865476f, -0.9238795325112867f,
    -1.0f,                 -0.9238795325112867f, -0.7071067811865476f, -0.3826834323650898f,
     0.0f,                  0.3826834323650898f,  0.7071067811865476f,  0.9238795325112867f };

// G4[b][rc][fp] = {Gr(2fp), Gr(2fp+1), Gi(2fp), Gi(2fp+1)}, pre-scaled by s_b
__device__ __align__(16) float4 g_G4[9 * 9 * 8];
// basepoints padded to float4; frames padded to 3x float4 (rows)
__device__ __align__(16) float4 g_bp4[NVERT];
__device__ __align__(16) float4 g_fr4[NVERT * 3];

#define FMA_F32X2(acc, a, b) \
    asm("fma.rn.f32x2 %0, %1, %2, %0;" : "+l"(acc) : "l"(a), "l"(b))
#define UNPACK_F32X2(lo, hi, in) \
    asm("mov.b64 {%0, %1}, %2;" : "=r"(lo), "=r"(hi) : "l"(in))

// smem byte offsets
#define OFF_GS  0                        // 648 float4  = 10368 B
#define OFF_YS  10368                    // 32*144 floats = 18432 B ([v][rc][16])
#define OFF_YH  28800                    // 32*81 float4 = 41472 B ([v][b][rc], dup)
#define OFF_BS  70272                    // 16 floats
#define SMEMSZ  70336

// ---------------- pre-kernel: pack basepoints + frames ----------------
__global__ void build_aux_kernel(const float* __restrict__ basepoints,
                                 const float* __restrict__ frames) {
    int i = blockIdx.x * 256 + threadIdx.x;
    if (i >= NVERT) return;
    g_bp4[i] = make_float4(basepoints[i * 3 + 0], basepoints[i * 3 + 1],
                           basepoints[i * 3 + 2], 0.0f);
    #pragma unroll
    for (int k = 0; k < 3; k++)
        g_fr4[i * 3 + k] = make_float4(frames[i * 9 + k * 3 + 0],
                                       frames[i * 9 + k * 3 + 1],
                                       frames[i * 9 + k * 3 + 2], 0.0f);
}

// ---------------- pre-kernel: G4 = s_b * conj(DFT_16(k)), f-pair packed ----
__global__ void build_G_kernel(const float* __restrict__ kern) {
    int idx = blockIdx.x * 256 + threadIdx.x;     // (b*9 + rc)*8 + fp
    if (idx >= 9 * 9 * 8) return;
    int fp = idx & 7;
    int rc = (idx >> 3) % 9;
    int b  = idx / 72;
    int r = rc / 3, c = rc - 3 * r;
    float gr[2] = {0.0f, 0.0f}, gi[2] = {0.0f, 0.0f};
    for (int w = 0; w < 16; w++) {
        float cw = C16[(w * b) & 15];
        float sw = C16[((w * b) + 12) & 15];
        #pragma unroll
        for (int u = 0; u < 2; u++) {
            float k = kern[((r * 16 + w) * 3 + c) * 16 + (2 * fp + u)];
            gr[u] += k * cw;
            gi[u] += k * sw;
        }
    }
    float s = (b == 0 || b == 8) ? (1.0f / 16.0f) : (2.0f / 16.0f);
    g_G4[idx] = make_float4(gr[0] * s, gr[1] * s, gi[0] * s, gi[1] * s);
}

// ---------------- main kernel ----------------
__global__ void __launch_bounds__(THREADS, 3)
geoconv_fft_kernel(const int*   __restrict__ expmap,       // (B*NV, 3, 16, 2)
                   const float* __restrict__ bias,         // (16,)
                   float* __restrict__ out)                // (B*NV, 16, 16)
{
    extern __shared__ char smem[];
    float4* Gs  = reinterpret_cast<float4*>(smem + OFF_GS);
    float*  ys  = reinterpret_cast<float*>(smem + OFF_YS);   // [v][rc][16]
    float4* Yh4 = reinterpret_cast<float4*>(smem + OFF_YH);  // [v][b][rc] dup
    float*  bs  = reinterpret_cast<float*>(smem + OFF_BS);

    const int tid = threadIdx.x;
    const int gbase = blockIdx.x * VPB;

    // stage G4 and bias
    #pragma unroll
    for (int it = 0; it < 3; it++) {
        int i = tid + it * THREADS;
        if (i < 648) Gs[i] = g_G4[i];
    }
    if (tid < 16) bs[tid] = bias[tid];

    // --- P1: gather + center + rotate; slot = (vl, d), 512 slots / 288 thr ---
    for (int s = tid; s < VPB * 16; s += THREADS) {
        const int vl = s >> 4;
        const int d  = s & 15;
        const int g  = gbase + vl;
        const float4 bp = g_bp4[g];
        const float4 F0 = g_fr4[g * 3 + 0];
        const float4 F1 = g_fr4[g * 3 + 1];
        const float4 F2 = g_fr4[g * 3 + 2];

        const int2* em = reinterpret_cast<const int2*>(expmap);
        #pragma unroll
        for (int r = 0; r < 3; r++) {
            int2 e = em[(g * 3 + r) * 16 + d];             // {batch, vertex}
            float4 nb = g_bp4[e.x * NVv + e.y];            // single LDG.128
            float y0 = nb.x - bp.x;
            float y1 = nb.y - bp.y;
            float y2 = nb.z - bp.z;
            float* yb = ys + vl * 144 + r * 48 + d;        // [v][rc][16]
            yb[0]  = fmaf(F0.z, y2, fmaf(F0.y, y1, F0.x * y0));
            yb[16] = fmaf(F1.z, y2, fmaf(F1.y, y1, F1.x * y0));
            yb[32] = fmaf(F2.z, y2, fmaf(F2.y, y1, F2.x * y0));
        }
    }
    __syncthreads();

    // --- P1b: 9-bin real DFT (radix-2 parity split); thread = (v, rc) ---
    {
        const int v  = tid / 9;
        const int rc = tid - v * 9;
        const float4* yr4 = reinterpret_cast<const float4*>(ys + v * 144 + rc * 16);
        float4 q0 = yr4[0], q1 = yr4[1], q2 = yr4[2], q3 = yr4[3];
        const float yv[16] = {q0.x, q0.y, q0.z, q0.w, q1.x, q1.y, q1.z, q1.w,
                              q2.x, q2.y, q2.z, q2.w, q3.x, q3.y, q3.z, q3.w};
        float u[8], w[8];
        #pragma unroll
        for (int q = 0; q < 8; q++) {
            u[q] = yv[q] + yv[q + 8];
            w[q] = yv[q] - yv[q + 8];
        }
        float4* dst = Yh4 + v * 81 + rc;                   // [v][b][rc]
        #pragma unroll
        for (int b = 0; b < 9; b++) {
            float re = 0.0f, im = 0.0f;
            #pragma unroll
            for (int q = 0; q < 8; q++) {
                const float src = (b & 1) ? w[q] : u[q];
                re = fmaf(src,  C16[(q * b) & 15], re);          // + src cos
                im = fmaf(src, -C16[((q * b) + 12) & 15], im);   // - src sin
            }
            dst[b * 9] = make_float4(re, re, im, im);      // duplicated
        }
    }
    __syncthreads();

    // --- P2 (fused): thread = (v, fp); 1 vertex, features 2fp, 2fp+1 ---
    if (tid < 256) {
        const int fp = tid & 7;
        const int v  = tid >> 3;

        // parity-split IDFT accumulators: out[j]=oE+oO, out[j+8]=oE-oO, j=0..7
        float oE0[8], oO0[8], oE1[8], oO1[8];
        const float b0 = bs[2 * fp], b1 = bs[2 * fp + 1];
        #pragma unroll
        for (int j = 0; j < 8; j++) {
            oE0[j] = b0; oE1[j] = b1;
            oO0[j] = 0.0f; oO1[j] = 0.0f;
        }

        #pragma unroll
        for (int b = 0; b < 9; b++) {
            const ulonglong2* Yb = reinterpret_cast<const ulonglong2*>(Yh4 + v * 81 + b * 9);
            const ulonglong2* Gb = reinterpret_cast<const ulonglong2*>(Gs + b * 72 + fp);

            // 4-acc split: p=SumYrGr, q=SumYiGi, r=SumYrGi, s=SumYiGr
            unsigned long long ap = 0ull, aq = 0ull, ar = 0ull, as_ = 0ull;
            #pragma unroll
            for (int rc = 0; rc < 9; rc++) {
                ulonglong2 y = Yb[rc];          // (Yr,Yr),(Yi,Yi)  1x LDS.128
                ulonglong2 g = Gb[rc * 8];      // (Gr0,Gr1),(Gi0,Gi1) 1x LDS.128
                FMA_F32X2(ap,  y.x, g.x);
                FMA_F32X2(aq,  y.y, g.y);
                FMA_F32X2(ar,  y.x, g.y);
                FMA_F32X2(as_, y.y, g.x);
            }
            unsigned int p0, p1, q0, q1, r0, r1, s0, s1;
            UNPACK_F32X2(p0, p1, ap);
            UNPACK_F32X2(q0, q1, aq);
            UNPACK_F32X2(r0, r1, ar);
            UNPACK_F32X2(s0, s1, as_);
            float Cr0 = __uint_as_float(p0) - __uint_as_float(q0);
            float Cr1 = __uint_as_float(p1) - __uint_as_float(q1);
            float Ci0 = __uint_as_float(r0) + __uint_as_float(s0);
            float Ci1 = __uint_as_float(r1) + __uint_as_float(s1);

            #pragma unroll
            for (int j = 0; j < 8; j++) {
                const float cj = C16[(j * b) & 15];
                const float sj = C16[((j * b) + 12) & 15];
                if ((b & 1) == 0) {
                    oE0[j] = fmaf(Cr0, cj, oE0[j]);
                    oE0[j] = fmaf(Ci0, -sj, oE0[j]);
                    oE1[j] = fmaf(Cr1, cj, oE1[j]);
                    oE1[j] = fmaf(Ci1, -sj, oE1[j]);
                } else {
                    oO0[j] = fmaf(Cr0, cj, oO0[j]);
                    oO0[j] = fmaf(Ci0, -sj, oO0[j]);
                    oO1[j] = fmaf(Cr1, cj, oO1[j]);
                    oO1[j] = fmaf(Ci1, -sj, oO1[j]);
                }
            }
        }

        // combine parity halves, relu, store (features 2fp, 2fp+1)
        float2* op = reinterpret_cast<float2*>(out + ((gbase + v) * 16) * 16 + 2 * fp);
        #pragma unroll
        for (int j = 0; j < 8; j++) {
            op[j * 8]       = make_float2(fmaxf(oE0[j] + oO0[j], 0.0f),
                                          fmaxf(oE1[j] + oO1[j], 0.0f));
            op[(j + 8) * 8] = make_float2(fmaxf(oE0[j] - oO0[j], 0.0f),
                                          fmaxf(oE1[j] - oO1[j], 0.0f));
        }
    }
}

// ---------------- launch ----------------
extern "C" void kernel_launch(void* const* d_in, const int* in_sizes, int n_in,
                              void* d_out, int out_size)
{
    const float* basepoints = (const float*)d_in[0];   // (B, NV, 3)
    const float* frames     = (const float*)d_in[1];   // (B, NV, 3, 3)
    const int*   expmap     = (const int*)  d_in[2];   // (B, NV, 3, 16, 2)
    const float* kern       = (const float*)d_in[3];   // (3, 16, 3, 16)
    const float* bias       = (const float*)d_in[4];   // (16,)
    float*       out        = (float*)d_out;           // (B, NV, 16, 16)

    cudaFuncSetAttribute(geoconv_fft_kernel,
                         cudaFuncAttributeMaxDynamicSharedMemorySize, SMEMSZ);

    int total_verts = in_sizes[0] / 3;                 // 200000
    int blocks = total_verts / VPB;                    // 6250

    build_aux_kernel<<<(NVERT + 255) / 256, 256>>>(basepoints, frames);
    build_G_kernel<<<3, 256>>>(kern);
    geoconv_fft_kernel<<<blocks, THREADS, SMEMSZ>>>(expmap, bias, out);
}

// round 14
// speedup vs baseline: 1.2187x; 1.2187x over previous
#include <cuda_runtime.h>
#include <cstdint>

// ============================================================================
// Geodesic patch conv via frequency domain (NDIRS=16 circular correlation):
//   Yhat[v,rc,b] = DFT_16(y[v,rc,:])   (9 half-spectrum bins, (re,im) float2)
//   out[v,j,f]   = relu( bias[f] + sum_b Re{ (sum_rc Yhat*G) e^{+i 2pi jb/16} } )
// Radix-2 parity splits halve both DFT stages; twiddles are constexpr imms.
// P2: thread = (vertex, f-pair); batched Y loads + 4-acc split (no negation).
// ============================================================================

#define NVv     50000
#define NVERT   200000
#define VPB     32
#define THREADS 288            // 9 warps; 32*9=288 exact for P1b

// cos(k * 22.5 deg), k = 0..15.  sin(k*22.5) = C16[(k+12)&15]
__device__ constexpr float C16[16] = {
     1.0f,                  0.9238795325112867f,  0.7071067811865476f,  0.3826834323650898f,
     0.0f,                 -0.3826834323650898f, -0.7071067811865476f, -0.9238795325112867f,
    -1.0f,                 -0.9238795325112867f, -0.7071067811865476f, -0.3826834323650898f,
     0.0f,                  0.3826834323650898f,  0.7071067811865476f,  0.9238795325112867f };

// G4[b][rc][fp] = {Gr(2fp), Gr(2fp+1), Gi(2fp), Gi(2fp+1)}, pre-scaled by s_b
__device__ __align__(16) float4 g_G4[9 * 9 * 8];
// basepoints padded to float4; frames padded to 3x float4 (rows)
__device__ __align__(16) float4 g_bp4[NVERT];
__device__ __align__(16) float4 g_fr4[NVERT * 3];

#define FMA_F32X2(acc, a, b) \
    asm("fma.rn.f32x2 %0, %1, %2, %0;" : "+l"(acc) : "l"(a), "l"(b))
#define PACK_F32X2(out, lo, hi) \
    asm("mov.b64 %0, {%1, %2};" : "=l"(out) : "r"(lo), "r"(hi))
#define UNPACK_F32X2(lo, hi, in) \
    asm("mov.b64 {%0, %1}, %2;" : "=r"(lo), "=r"(hi) : "l"(in))

// smem byte offsets
#define OFF_GS  0                        // 648 float4 = 10368 B
#define OFF_YS  10368                    // 32 * 144 floats = 18432 B  ([v][rc][16])
#define OFF_YH  28800                    // 32 * 90 float2 = 23040 B   ([v][b*10+rc])
#define OFF_BS  51840                    // 16 floats
#define SMEMSZ  51904

// ---------------- single pre-kernel: pack bp/frames + build G4 ----------------
__global__ void build_pre_kernel(const float* __restrict__ basepoints,
                                 const float* __restrict__ frames,
                                 const float* __restrict__ kern) {
    int i = blockIdx.x * 256 + threadIdx.x;
    if (i < NVERT) {
        g_bp4[i] = make_float4(basepoints[i * 3 + 0], basepoints[i * 3 + 1],
                               basepoints[i * 3 + 2], 0.0f);
        #pragma unroll
        for (int k = 0; k < 3; k++)
            g_fr4[i * 3 + k] = make_float4(frames[i * 9 + k * 3 + 0],
                                           frames[i * 9 + k * 3 + 1],
                                           frames[i * 9 + k * 3 + 2], 0.0f);
    }
    if (i < 9 * 9 * 8) {                  // (b*9 + rc)*8 + fp
        int fp = i & 7;
        int rc = (i >> 3) % 9;
        int b  = i / 72;
        int r = rc / 3, c = rc - 3 * r;
        float gr[2] = {0.0f, 0.0f}, gi[2] = {0.0f, 0.0f};
        for (int w = 0; w < 16; w++) {
            float cw = C16[(w * b) & 15];
            float sw = C16[((w * b) + 12) & 15];
            #pragma unroll
            for (int u = 0; u < 2; u++) {
                float k = kern[((r * 16 + w) * 3 + c) * 16 + (2 * fp + u)];
                gr[u] += k * cw;
                gi[u] += k * sw;
            }
        }
        float s = (b == 0 || b == 8) ? (1.0f / 16.0f) : (2.0f / 16.0f);
        g_G4[i] = make_float4(gr[0] * s, gr[1] * s, gi[0] * s, gi[1] * s);
    }
}

// one (rc) complex MAC, 4-acc split: ap+=YrGr, aq+=YiGi, ar+=YrGi, as+=YiGr
#define RCSTEP4(yr, yi, gv) do { \
    unsigned long long _yrr, _yii, _ghr, _ghi; \
    PACK_F32X2(_yrr, __float_as_uint(yr), __float_as_uint(yr)); \
    PACK_F32X2(_yii, __float_as_uint(yi), __float_as_uint(yi)); \
    PACK_F32X2(_ghr, __float_as_uint((gv).x), __float_as_uint((gv).y)); \
    PACK_F32X2(_ghi, __float_as_uint((gv).z), __float_as_uint((gv).w)); \
    FMA_F32X2(a_p, _yrr, _ghr); \
    FMA_F32X2(a_q, _yii, _ghi); \
    FMA_F32X2(a_r, _yrr, _ghi); \
    FMA_F32X2(a_s, _yii, _ghr); \
} while (0)

// ---------------- main kernel ----------------
__global__ void __launch_bounds__(THREADS, 3)
geoconv_fft_kernel(const int*   __restrict__ expmap,       // (B*NV, 3, 16, 2)
                   const float* __restrict__ bias,         // (16,)
                   float* __restrict__ out)                // (B*NV, 16, 16)
{
    extern __shared__ char smem[];
    float4* Gs = reinterpret_cast<float4*>(smem + OFF_GS);
    float*  ys = reinterpret_cast<float*>(smem + OFF_YS);   // [v][rc][16]
    float2* Yh = reinterpret_cast<float2*>(smem + OFF_YH);  // [v][b*10 + rc]
    float*  bs = reinterpret_cast<float*>(smem + OFF_BS);

    const int tid = threadIdx.x;
    const int gbase = blockIdx.x * VPB;

    // stage G4 and bias
    #pragma unroll
    for (int it = 0; it < 3; it++) {
        int i = tid + it * THREADS;
        if (i < 648) Gs[i] = g_G4[i];
    }
    if (tid < 16) bs[tid] = bias[tid];

    // --- P1: gather + center + rotate; slot = (vl, d), 512 slots / 288 thr ---
    for (int s = tid; s < VPB * 16; s += THREADS) {
        const int vl = s >> 4;
        const int d  = s & 15;
        const int g  = gbase + vl;
        const float4 bp = g_bp4[g];
        const float4 F0 = g_fr4[g * 3 + 0];
        const float4 F1 = g_fr4[g * 3 + 1];
        const float4 F2 = g_fr4[g * 3 + 2];

        const int2* em = reinterpret_cast<const int2*>(expmap);
        #pragma unroll
        for (int r = 0; r < 3; r++) {
            int2 e = em[(g * 3 + r) * 16 + d];             // {batch, vertex}
            float4 nb = g_bp4[e.x * NVv + e.y];            // single LDG.128
            float y0 = nb.x - bp.x;
            float y1 = nb.y - bp.y;
            float y2 = nb.z - bp.z;
            float* yb = ys + vl * 144 + r * 48 + d;        // [v][rc][16]
            yb[0]  = fmaf(F0.z, y2, fmaf(F0.y, y1, F0.x * y0));
            yb[16] = fmaf(F1.z, y2, fmaf(F1.y, y1, F1.x * y0));
            yb[32] = fmaf(F2.z, y2, fmaf(F2.y, y1, F2.x * y0));
        }
    }
    __syncthreads();

    // --- P1b: 9-bin real DFT with radix-2 parity split; thread = (v, rc) ---
    {
        const int v  = tid / 9;
        const int rc = tid - v * 9;
        const float4* yr4 = reinterpret_cast<const float4*>(ys + v * 144 + rc * 16);
        float4 q0 = yr4[0], q1 = yr4[1], q2 = yr4[2], q3 = yr4[3];
        const float yv[16] = {q0.x, q0.y, q0.z, q0.w, q1.x, q1.y, q1.z, q1.w,
                              q2.x, q2.y, q2.z, q2.w, q3.x, q3.y, q3.z, q3.w};
        float u[8], w[8];
        #pragma unroll
        for (int q = 0; q < 8; q++) {
            u[q] = yv[q] + yv[q + 8];
            w[q] = yv[q] - yv[q + 8];
        }
        float2* dst = Yh + v * 90 + rc;
        #pragma unroll
        for (int b = 0; b < 9; b++) {
            float re = 0.0f, im = 0.0f;
            #pragma unroll
            for (int q = 0; q < 8; q++) {
                const float src = (b & 1) ? w[q] : u[q];
                re = fmaf(src,  C16[(q * b) & 15], re);          // + src cos
                im = fmaf(src, -C16[((q * b) + 12) & 15], im);   // - src sin
            }
            dst[b * 10] = make_float2(re, im);
        }
    }
    __syncthreads();

    // --- P2 (fused): thread = (v, fp); 1 vertex, features 2fp, 2fp+1 ---
    if (tid < 256) {
        const int fp = tid & 7;
        const int v  = tid >> 3;

        // parity-split IDFT accumulators: out[j]=oE+oO, out[j+8]=oE-oO, j=0..7
        float oE0[8], oO0[8], oE1[8], oO1[8];
        const float b0 = bs[2 * fp], b1 = bs[2 * fp + 1];
        #pragma unroll
        for (int j = 0; j < 8; j++) {
            oE0[j] = b0; oE1[j] = b1;
            oO0[j] = 0.0f; oO1[j] = 0.0f;
        }

        #pragma unroll
        for (int b = 0; b < 9; b++) {
            // load 9 (Yr,Yi) pairs for this (v,b): 4x LDS.128 + 1x LDS.64
            const float4* Yb4 = reinterpret_cast<const float4*>(Yh + v * 90 + b * 10);
            float4 ya = Yb4[0], yb_ = Yb4[1], yc = Yb4[2], yd = Yb4[3];
            float2 ye = *reinterpret_cast<const float2*>(Yh + v * 90 + b * 10 + 8);

            const float4* Gb = Gs + b * 72 + fp;   // [b][rc][fp], rc stride 8
            unsigned long long a_p = 0ull, a_q = 0ull, a_r = 0ull, a_s = 0ull;
            RCSTEP4(ya.x,  ya.y,  Gb[0]);
            RCSTEP4(ya.z,  ya.w,  Gb[8]);
            RCSTEP4(yb_.x, yb_.y, Gb[16]);
            RCSTEP4(yb_.z, yb_.w, Gb[24]);
            RCSTEP4(yc.x,  yc.y,  Gb[32]);
            RCSTEP4(yc.z,  yc.w,  Gb[40]);
            RCSTEP4(yd.x,  yd.y,  Gb[48]);
            RCSTEP4(yd.z,  yd.w,  Gb[56]);
            RCSTEP4(ye.x,  ye.y,  Gb[64]);

            unsigned int p0, p1, q0_, q1_, r0, r1, s0, s1;
            UNPACK_F32X2(p0, p1, a_p);
            UNPACK_F32X2(q0_, q1_, a_q);
            UNPACK_F32X2(r0, r1, a_r);
            UNPACK_F32X2(s0, s1, a_s);
            float Cr0 = __uint_as_float(p0) - __uint_as_float(q0_);
            float Cr1 = __uint_as_float(p1) - __uint_as_float(q1_);
            float Ci0 = __uint_as_float(r0) + __uint_as_float(s0);
            float Ci1 = __uint_as_float(r1) + __uint_as_float(s1);

            #pragma unroll
            for (int j = 0; j < 8; j++) {
                const float cj = C16[(j * b) & 15];
                const float sj = C16[((j * b) + 12) & 15];
                if ((b & 1) == 0) {
                    oE0[j] = fmaf(Cr0, cj, oE0[j]);
                    oE0[j] = fmaf(Ci0, -sj, oE0[j]);
                    oE1[j] = fmaf(Cr1, cj, oE1[j]);
                    oE1[j] = fmaf(Ci1, -sj, oE1[j]);
                } else {
                    oO0[j] = fmaf(Cr0, cj, oO0[j]);
                    oO0[j] = fmaf(Ci0, -sj, oO0[j]);
                    oO1[j] = fmaf(Cr1, cj, oO1[j]);
                    oO1[j] = fmaf(Ci1, -sj, oO1[j]);
                }
            }
        }

        // combine parity halves, relu, store (features 2fp, 2fp+1)
        float2* op = reinterpret_cast<float2*>(out + ((gbase + v) * 16) * 16 + 2 * fp);
        #pragma unroll
        for (int j = 0; j < 8; j++) {
            op[j * 8]       = make_float2(fmaxf(oE0[j] + oO0[j], 0.0f),
                                          fmaxf(oE1[j] + oO1[j], 0.0f));
            op[(j + 8) * 8] = make_float2(fmaxf(oE0[j] - oO0[j], 0.0f),
                                          fmaxf(oE1[j] - oO1[j], 0.0f));
        }
    }
}

// ---------------- launch ----------------
extern "C" void kernel_launch(void* const* d_in, const int* in_sizes, int n_in,
                              void* d_out, int out_size)
{
    const float* basepoints = (const float*)d_in[0];   // (B, NV, 3)
    const float* frames     = (const float*)d_in[1];   // (B, NV, 3, 3)
    const int*   expmap     = (const int*)  d_in[2];   // (B, NV, 3, 16, 2)
    const float* kern       = (const float*)d_in[3];   // (3, 16, 3, 16)
    const float* bias       = (const float*)d_in[4];   // (16,)
    float*       out        = (float*)d_out;           // (B, NV, 16, 16)

    cudaFuncSetAttribute(geoconv_fft_kernel,
                         cudaFuncAttributeMaxDynamicSharedMemorySize, SMEMSZ);

    int total_verts = in_sizes[0] / 3;                 // 200000
    int blocks = total_verts / VPB;                    // 6250

    build_pre_kernel<<<(NVERT + 255) / 256, 256>>>(basepoints, frames, kern);
    geoconv_fft_kernel<<<blocks, THREADS, SMEMSZ>>>(expmap, bias, out);
}